// round 9
// baseline (speedup 1.0000x reference)
#include <cuda_runtime.h>
#include <cuda_bf16.h>

#define NMAX 100000
#define FDIM 128
#define DDIM 32
#define LLEN 100
#define RNUM 5

typedef unsigned long long ull;

// Scratch (static device globals — no allocation in kernel_launch)
__device__ float g_proj[NMAX * DDIM];   // features @ W_feat + b_feat, per node
__device__ int   g_skill[NMAX];         // (int)features[n,0]

// ---- packed fp32x2 helpers (Blackwell FFMA2; IEEE-identical to scalar FFMA) ----
__device__ __forceinline__ ull splat2(float s) {
    ull d;
    asm("mov.b64 %0, {%1, %1};" : "=l"(d) : "f"(s));
    return d;
}
__device__ __forceinline__ void ffma2(ull& acc, ull a, ull b) {
    asm("fma.rn.f32x2 %0, %1, %2, %0;" : "+l"(acc) : "l"(a), "l"(b));
}

// one f-step: two row-scalars against an 8-col weight row (2 splat : 8 ffma2 : 2 LDS.128)
__device__ __forceinline__ void pstep(float xs0, float xs1, const float* wrow,
                                      ull& a00, ull& a01, ull& a02, ull& a03,
                                      ull& a10, ull& a11, ull& a12, ull& a13)
{
    ulonglong2 wA = *(const ulonglong2*)(wrow);       // cols 0..3 of the octet
    ulonglong2 wB = *(const ulonglong2*)(wrow + 4);   // cols 4..7
    ull s0 = splat2(xs0), s1 = splat2(xs1);
    ffma2(a00, s0, wA.x); ffma2(a01, s0, wA.y); ffma2(a02, s0, wB.x); ffma2(a03, s0, wB.y);
    ffma2(a10, s1, wA.x); ffma2(a11, s1, wA.y); ffma2(a12, s1, wB.x); ffma2(a13, s1, wB.y);
}

// ---------------------------------------------------------------------------
// Kernel 1: proj = feat @ W_feat + b_feat, skill = (int)feat[:,0].
// Thread = 2 rows x 8 cols, packed f32x2 accumulators. Warp = 16 rows x 32 cols.
// CTA = 128 rows. Row data via LDG.128 (4 lanes/row dedup in L1), weights LDS.128.
// ---------------------------------------------------------------------------
__global__ __launch_bounds__(256) void k_proj(const float* __restrict__ feat,
                                              const float* __restrict__ Wf,
                                              const float* __restrict__ bf,
                                              int N)
{
    __shared__ __align__(16) float sW[FDIM * DDIM];   // 16 KB W_feat[f][d]
    __shared__ __align__(16) float sB[DDIM];

    for (int i = threadIdx.x; i < FDIM * DDIM; i += 256) sW[i] = Wf[i];
    if (threadIdx.x < DDIM) sB[threadIdx.x] = bf[threadIdx.x];
    __syncthreads();

    const int lane = threadIdx.x & 31;
    const int warp = threadIdx.x >> 5;
    const int dq   = lane & 3;          // col octet: cols dq*8 .. dq*8+7
    const int rg   = lane >> 2;         // 0..7 row-pair within warp
    const int rb   = (blockIdx.x * 8 + warp) * 16 + rg * 2;   // rows rb, rb+1
    if (rb >= N) return;

    const int r0 = rb, r1 = min(rb + 1, N - 1);
    const float* p0 = feat + (size_t)r0 * FDIM;
    const float* p1 = feat + (size_t)r1 * FDIM;

    if (dq == 0) {   // skill = truncating int cast of feature 0
        g_skill[r0] = (int)p0[0];
        if (rb + 1 < N) g_skill[r1] = (int)p1[0];
    }

    ulonglong2 bA = *(const ulonglong2*)&sB[dq * 8];
    ulonglong2 bB = *(const ulonglong2*)&sB[dq * 8 + 4];
    ull a00 = bA.x, a01 = bA.y, a02 = bB.x, a03 = bB.y;
    ull a10 = bA.x, a11 = bA.y, a12 = bB.x, a13 = bB.y;

    #pragma unroll 8
    for (int f0 = 0; f0 < FDIM; f0 += 4) {
        float4 x0 = *(const float4*)(p0 + f0);
        float4 x1 = *(const float4*)(p1 + f0);
        pstep(x0.x, x1.x, &sW[(f0 + 0) * DDIM + dq * 8], a00,a01,a02,a03, a10,a11,a12,a13);
        pstep(x0.y, x1.y, &sW[(f0 + 1) * DDIM + dq * 8], a00,a01,a02,a03, a10,a11,a12,a13);
        pstep(x0.z, x1.z, &sW[(f0 + 2) * DDIM + dq * 8], a00,a01,a02,a03, a10,a11,a12,a13);
        pstep(x0.w, x1.w, &sW[(f0 + 3) * DDIM + dq * 8], a00,a01,a02,a03, a10,a11,a12,a13);
    }

    ulonglong2 s0a; s0a.x = a00; s0a.y = a01;
    ulonglong2 s0b; s0b.x = a02; s0b.y = a03;
    *(ulonglong2*)&g_proj[(size_t)r0 * DDIM + dq * 8]     = s0a;
    *(ulonglong2*)&g_proj[(size_t)r0 * DDIM + dq * 8 + 4] = s0b;
    if (rb + 1 < N) {
        ulonglong2 s1a; s1a.x = a10; s1a.y = a11;
        ulonglong2 s1b; s1b.x = a12; s1b.y = a13;
        *(ulonglong2*)&g_proj[(size_t)r1 * DDIM + dq * 8]     = s1a;
        *(ulonglong2*)&g_proj[(size_t)r1 * DDIM + dq * 8 + 4] = s1b;
    }
}

// ---------------------------------------------------------------------------
// Kernel 2: one CTA per batch element. Item-parallel gather (800 items =
// 100 l x 8 col-quads), register accumulators, no shuffle reductions.
// LN via smem partials (E[x^2]-mu^2). Output: [0:B*D]=src, [B*D:2BD]=dst.
// ---------------------------------------------------------------------------
__global__ __launch_bounds__(256) void k_main(const int* __restrict__ rnodes,
    const int* __restrict__ ridx, const int* __restrict__ dst_ids,
    const float* __restrict__ wstr, const float* __restrict__ bstr,
    const float* __restrict__ lng, const float* __restrict__ lnb,
    const float* __restrict__ Wgcn, const float* __restrict__ bgcn,
    const float* __restrict__ Wout, const float* __restrict__ bout,
    float* __restrict__ out, int B)
{
    __shared__ int   s_nodes[RNUM * LLEN];                    // 2 KB
    __shared__ float s_sim[LLEN];                             // sim count per l
    __shared__ float s_mu[LLEN], s_alpha[LLEN];
    __shared__ __align__(16) float s_hist[LLEN * DDIM];       // 12.8 KB
    __shared__ __align__(16) float s_xW[LLEN * DDIM];         // 12.8 KB (partials overlay)
    __shared__ float s_ws[DDIM], s_bs[DDIM], s_lg[DDIM], s_lb[DDIM], s_bg[DDIM];
    __shared__ float s_part[8][DDIM];
    __shared__ int   s_ridx[RNUM];
    __shared__ int   s_cur, s_dst;

    float* s_p1 = s_xW;          // [800] per-item sum
    float* s_p2 = s_xW + 800;    // [800] per-item sumsq

    const int b = blockIdx.x;
    const int tid = threadIdx.x, lane = tid & 31, warp = tid >> 5;

    if (tid < DDIM) {
        s_ws[tid] = wstr[tid]; s_bs[tid] = bstr[tid];
        s_lg[tid] = lng[tid];  s_lb[tid] = lnb[tid];
        s_bg[tid] = bgcn[tid];
    }
    if (tid < RNUM) s_ridx[tid] = ridx[b * RNUM + tid];
    if (tid == 0) {
        int dn = dst_ids[b];
        s_dst = dn;
        s_cur = g_skill[dn];
    }
    __syncthreads();

    // stage node ids (100 consecutive ints per retrieved row)
    for (int i = tid; i < RNUM * LLEN; i += 256) {
        int r = i / LLEN, c = i - r * LLEN;
        s_nodes[i] = rnodes[s_ridx[r] * LLEN + c];
    }
    __syncthreads();

    // sim count per l (threads 0..99; 5 independent scattered 4B loads)
    int simc = 0;
    if (tid < LLEN) {
        const int cur = s_cur;
        #pragma unroll
        for (int r = 0; r < RNUM; r++)
            simc += (g_skill[s_nodes[r * LLEN + tid]] == cur) ? 1 : 0;
    }

    // gather: 800 items, <=4 per thread, 5 independent float4 loads each (MLP ~20)
    float4 hreg[4];
    #pragma unroll
    for (int it = 0; it < 4; it++) {
        int i = tid + it * 256;
        float4 a = make_float4(0.f, 0.f, 0.f, 0.f);
        if (i < 8 * LLEN) {
            int l = i >> 3, q = i & 7;
            #pragma unroll
            for (int r = 0; r < RNUM; r++) {
                int nd = s_nodes[r * LLEN + l];
                float4 v = *(const float4*)&g_proj[(size_t)nd * DDIM + q * 4];
                a.x += v.x; a.y += v.y; a.z += v.z; a.w += v.w;
            }
        }
        hreg[it] = a;
    }
    if (tid < LLEN) s_sim[tid] = (float)simc;

    // valid[b] = count of demo_nodes[b,0,l] > 0 (barrier also publishes s_sim)
    const int valid = __syncthreads_count(tid < LLEN && s_nodes[tid] > 0);

    // apply sim-linear + bias (pre-LN h), write LN partials
    #pragma unroll
    for (int it = 0; it < 4; it++) {
        int i = tid + it * 256;
        if (i < 8 * LLEN) {
            int l = i >> 3, q = i & 7;
            float sim = s_sim[l];
            float4 wv = *(const float4*)&s_ws[q * 4];
            float4 bv = *(const float4*)&s_bs[q * 4];
            float4 h = hreg[it];
            h.x = fmaf(sim, wv.x, h.x) * (1.f / RNUM) + bv.x;
            h.y = fmaf(sim, wv.y, h.y) * (1.f / RNUM) + bv.y;
            h.z = fmaf(sim, wv.z, h.z) * (1.f / RNUM) + bv.z;
            h.w = fmaf(sim, wv.w, h.w) * (1.f / RNUM) + bv.w;
            hreg[it] = h;
            s_p1[i] = h.x + h.y + h.z + h.w;
            s_p2[i] = fmaf(h.x, h.x, fmaf(h.y, h.y, fmaf(h.z, h.z, h.w * h.w)));
        }
    }
    __syncthreads();

    // LN stats: one thread per l
    if (tid < LLEN) {
        float s = 0.f, ss = 0.f;
        #pragma unroll
        for (int q = 0; q < 8; q++) { s += s_p1[tid * 8 + q]; ss += s_p2[tid * 8 + q]; }
        float mu = s * (1.f / DDIM);
        float var = ss * (1.f / DDIM) - mu * mu;
        s_mu[tid] = mu;
        s_alpha[tid] = rsqrtf(var + 1e-5f);
    }
    __syncthreads();

    // apply LN, write s_hist
    #pragma unroll
    for (int it = 0; it < 4; it++) {
        int i = tid + it * 256;
        if (i < 8 * LLEN) {
            int l = i >> 3, q = i & 7;
            float mu = s_mu[l], al = s_alpha[l];
            float4 g4 = *(const float4*)&s_lg[q * 4];
            float4 b4 = *(const float4*)&s_lb[q * 4];
            float4 h = hreg[it];
            h.x = (h.x - mu) * al * g4.x + b4.x;
            h.y = (h.y - mu) * al * g4.y + b4.y;
            h.z = (h.z - mu) * al * g4.z + b4.z;
            h.w = (h.w - mu) * al * g4.w + b4.w;
            *(float4*)&s_hist[l * DDIM + q * 4] = h;
        }
    }
    __syncthreads();

    // xW = hist @ W_gcn (warp per l, lane = output column)
    {
        float wg[DDIM];
        #pragma unroll
        for (int k = 0; k < DDIM; k++) wg[k] = Wgcn[k * DDIM + lane];
        for (int l = warp; l < LLEN; l += 8) {
            float acc = 0.f;
            #pragma unroll
            for (int k0 = 0; k0 < DDIM; k0 += 4) {
                float4 hv = *(const float4*)&s_hist[l * DDIM + k0];
                acc = fmaf(hv.x, wg[k0 + 0], acc);
                acc = fmaf(hv.y, wg[k0 + 1], acc);
                acc = fmaf(hv.z, wg[k0 + 2], acc);
                acc = fmaf(hv.w, wg[k0 + 3], acc);
            }
            s_xW[l * DDIM + lane] = acc;
        }
    }
    __syncthreads();

    // chain GCN + relu + mean over L (per-warp partials, deterministic)
    float lsum = 0.f;
    for (int l = warp; l < LLEN; l += 8) {
        bool has_in = (l >= 1 && l < valid);
        float o = s_xW[l * DDIM + lane];
        if (has_in) {
            float degp = (l >= 2 && (l - 1) < valid) ? 2.f : 1.f;
            o = o * 0.5f + s_xW[(l - 1) * DDIM + lane] * rsqrtf(degp * 2.f);
        }
        lsum += fmaxf(o + s_bg[lane], 0.f);
    }
    s_part[warp][lane] = lsum;
    __syncthreads();

    if (warp == 0) {
        float p = 0.f;
        #pragma unroll
        for (int w = 0; w < 8; w++) p += s_part[w][lane];
        p *= (1.f / LLEN);
        float e = bout[lane];
        #pragma unroll
        for (int k = 0; k < DDIM; k++) {
            float pk = __shfl_sync(0xffffffffu, p, k);
            e = fmaf(pk, Wout[k * DDIM + lane], e);
        }
        out[b * DDIM + lane] = e;                      // src_emb
    } else if (warp == 1) {
        float p = g_proj[(size_t)s_dst * DDIM + lane];
        float e = bout[lane];
        #pragma unroll
        for (int k = 0; k < DDIM; k++) {
            float pk = __shfl_sync(0xffffffffu, p, k);
            e = fmaf(pk, Wout[k * DDIM + lane], e);
        }
        out[B * DDIM + b * DDIM + lane] = e;           // dst_emb
    }
}

extern "C" void kernel_launch(void* const* d_in, const int* in_sizes, int n_in,
                              void* d_out, int out_size)
{
    const float* feat   = (const float*)d_in[0];   // [N, 128]
    const int*   rnodes = (const int*)  d_in[1];   // [P, 100]
    const int*   ridx   = (const int*)  d_in[2];   // [B, 5]
    const int*   dst    = (const int*)  d_in[4];   // [B]
    const float* Wf = (const float*)d_in[6];
    const float* bf = (const float*)d_in[7];
    const float* ws = (const float*)d_in[8];
    const float* bs = (const float*)d_in[9];
    const float* lg = (const float*)d_in[10];
    const float* lb = (const float*)d_in[11];
    const float* Wg = (const float*)d_in[12];
    const float* bg = (const float*)d_in[13];
    const float* Wo = (const float*)d_in[14];
    const float* bo = (const float*)d_in[15];
    float* out = (float*)d_out;

    int N = in_sizes[0] / FDIM;
    int B = in_sizes[4];
    if (N > NMAX) N = NMAX;

    int nblk = (N + 127) / 128;
    k_proj<<<nblk, 256>>>(feat, Wf, bf, N);
    k_main<<<B, 256>>>(rnodes, ridx, dst, ws, bs, lg, lb, Wg, bg, Wo, bo, out, B);
}

// round 14
// speedup vs baseline: 1.0756x; 1.0756x over previous
#include <cuda_runtime.h>
#include <cuda_bf16.h>

#define NMAX 100000
#define FDIM 128
#define DDIM 32
#define LLEN 100
#define HALF 50
#define RNUM 5
#define BMAX 4096

// Scratch (static device globals — no allocation in kernel_launch)
__device__ float g_proj[NMAX * DDIM];   // features @ W_feat + b_feat, per node
__device__ int   g_skill[NMAX];         // (int)features[n,0]
__device__ float g_pool[BMAX * 2 * DDIM]; // per-half pooled GCN partial sums

__device__ __forceinline__ void fma4(float4& acc, float s, const float4& wv) {
    acc.x = fmaf(s, wv.x, acc.x);
    acc.y = fmaf(s, wv.y, acc.y);
    acc.z = fmaf(s, wv.z, acc.z);
    acc.w = fmaf(s, wv.w, acc.w);
}

// ---------------------------------------------------------------------------
// Kernel 1 (R4 scalar version, measured ~29us — FFMA2 variant regressed):
// proj = feat @ W_feat + b_feat, skill = (int)feat[:,0].
// Thread = 4 rows x 4 cols. Warp = 16 rows x 32 cols. CTA = 128 rows.
// ---------------------------------------------------------------------------
__global__ __launch_bounds__(256) void k_proj(const float* __restrict__ feat,
                                              const float* __restrict__ Wf,
                                              const float* __restrict__ bf,
                                              int N)
{
    __shared__ __align__(16) float sW[FDIM * DDIM];   // 16 KB W_feat[f][d]
    __shared__ __align__(16) float sB[DDIM];

    for (int i = threadIdx.x; i < FDIM * DDIM; i += 256) sW[i] = Wf[i];
    if (threadIdx.x < DDIM) sB[threadIdx.x] = bf[threadIdx.x];
    __syncthreads();

    const int lane = threadIdx.x & 31;
    const int warp = threadIdx.x >> 5;
    const int dq   = lane & 7;          // col group: cols dq*4 .. dq*4+3
    const int rg   = lane >> 3;         // row group within warp
    const int rb   = (blockIdx.x * 8 + warp) * 16 + rg * 4;  // rows rb..rb+3
    if (rb >= N) return;

    const int r0 = rb,                 r1 = min(rb + 1, N - 1);
    const int r2 = min(rb + 2, N - 1), r3 = min(rb + 3, N - 1);
    const float* p0 = feat + (size_t)r0 * FDIM;
    const float* p1 = feat + (size_t)r1 * FDIM;
    const float* p2 = feat + (size_t)r2 * FDIM;
    const float* p3 = feat + (size_t)r3 * FDIM;

    if (dq == 0) {   // skill = truncating int cast of feature 0
        g_skill[r0] = (int)p0[0];
        if (rb + 1 < N) g_skill[r1] = (int)p1[0];
        if (rb + 2 < N) g_skill[r2] = (int)p2[0];
        if (rb + 3 < N) g_skill[r3] = (int)p3[0];
    }

    float4 bias = *(const float4*)&sB[dq * 4];
    float4 a0 = bias, a1 = bias, a2 = bias, a3 = bias;

    #pragma unroll 8
    for (int f0 = 0; f0 < FDIM; f0 += 4) {
        float4 x0 = *(const float4*)(p0 + f0);
        float4 x1 = *(const float4*)(p1 + f0);
        float4 x2 = *(const float4*)(p2 + f0);
        float4 x3 = *(const float4*)(p3 + f0);
        float4 w0 = *(const float4*)&sW[(f0 + 0) * DDIM + dq * 4];
        float4 w1 = *(const float4*)&sW[(f0 + 1) * DDIM + dq * 4];
        float4 w2 = *(const float4*)&sW[(f0 + 2) * DDIM + dq * 4];
        float4 w3 = *(const float4*)&sW[(f0 + 3) * DDIM + dq * 4];
        fma4(a0, x0.x, w0); fma4(a0, x0.y, w1); fma4(a0, x0.z, w2); fma4(a0, x0.w, w3);
        fma4(a1, x1.x, w0); fma4(a1, x1.y, w1); fma4(a1, x1.z, w2); fma4(a1, x1.w, w3);
        fma4(a2, x2.x, w0); fma4(a2, x2.y, w1); fma4(a2, x2.z, w2); fma4(a2, x2.w, w3);
        fma4(a3, x3.x, w0); fma4(a3, x3.y, w1); fma4(a3, x3.z, w2); fma4(a3, x3.w, w3);
    }

    *(float4*)&g_proj[(size_t)r0 * DDIM + dq * 4] = a0;
    if (rb + 1 < N) *(float4*)&g_proj[(size_t)r1 * DDIM + dq * 4] = a1;
    if (rb + 2 < N) *(float4*)&g_proj[(size_t)r2 * DDIM + dq * 4] = a2;
    if (rb + 3 < N) *(float4*)&g_proj[(size_t)r3 * DDIM + dq * 4] = a3;
}

// ---------------------------------------------------------------------------
// Kernel 2: grid (B, 2). CTA (b, half) handles l in [half*50, half*50+50),
// computing hist/xW also for boundary row l=49 when half=1 (chain message
// into l=50). Pooled relu-sum partial -> g_pool[b][half][:]. No shuffles.
// ---------------------------------------------------------------------------
__global__ __launch_bounds__(256) void k_mainA(const int* __restrict__ rnodes,
    const int* __restrict__ ridx, const int* __restrict__ dst_ids,
    const float* __restrict__ wstr, const float* __restrict__ bstr,
    const float* __restrict__ lng, const float* __restrict__ lnb,
    const float* __restrict__ Wgcn, const float* __restrict__ bgcn)
{
    __shared__ int   s_nodes[RNUM * LLEN];                    // 2 KB (full id table)
    __shared__ float s_sim[HALF + 1];
    __shared__ float s_mu[HALF + 1], s_alpha[HALF + 1];
    __shared__ __align__(16) float s_hist[(HALF + 1) * DDIM]; // 6.5 KB
    __shared__ __align__(16) float s_xW[(HALF + 1) * DDIM];   // 6.5 KB (partial overlay)
    __shared__ float s_ws[DDIM], s_bs[DDIM], s_lg[DDIM], s_lb[DDIM], s_bg[DDIM];
    __shared__ float s_part[8][DDIM];
    __shared__ int   s_ridx[RNUM];
    __shared__ int   s_cur;

    float* s_p1 = s_xW;                    // [(HALF+1)*8] per-item sum
    float* s_p2 = s_xW + (HALF + 1) * 8;   // [(HALF+1)*8] per-item sumsq

    const int b    = blockIdx.x;
    const int half = blockIdx.y;
    const int l0   = half ? (HALF - 1) : 0;        // first local row's global l
    const int nr   = half ? (HALF + 1) : HALF;     // local hist/xW rows
    const int tid = threadIdx.x, lane = tid & 31, warp = tid >> 5;

    if (tid < DDIM) {
        s_ws[tid] = wstr[tid]; s_bs[tid] = bstr[tid];
        s_lg[tid] = lng[tid];  s_lb[tid] = lnb[tid];
        s_bg[tid] = bgcn[tid];
    }
    if (tid < RNUM) s_ridx[tid] = ridx[b * RNUM + tid];
    if (tid == 0) s_cur = g_skill[dst_ids[b]];
    __syncthreads();

    // stage full node-id table (500 ints; 100 consecutive per retrieved row)
    for (int i = tid; i < RNUM * LLEN; i += 256) {
        int r = i / LLEN, c = i - r * LLEN;
        s_nodes[i] = rnodes[s_ridx[r] * LLEN + c];
    }
    __syncthreads();

    // sim count per local row (<=51 threads, 5 independent scattered loads)
    int simc = 0;
    if (tid < nr) {
        const int cur = s_cur;
        #pragma unroll
        for (int r = 0; r < RNUM; r++)
            simc += (g_skill[s_nodes[r * LLEN + l0 + tid]] == cur) ? 1 : 0;
    }

    // gather: nr*8 items (<=408), <=2 per thread, 5 independent float4 loads each
    const int nitems = nr * 8;
    float4 hreg[2];
    #pragma unroll
    for (int it = 0; it < 2; it++) {
        int i = tid + it * 256;
        float4 a = make_float4(0.f, 0.f, 0.f, 0.f);
        if (i < nitems) {
            int lr = i >> 3, q = i & 7;
            int l = l0 + lr;
            #pragma unroll
            for (int r = 0; r < RNUM; r++) {
                int nd = s_nodes[r * LLEN + l];
                float4 v = *(const float4*)&g_proj[(size_t)nd * DDIM + q * 4];
                a.x += v.x; a.y += v.y; a.z += v.z; a.w += v.w;
            }
        }
        hreg[it] = a;
    }
    if (tid < nr) s_sim[tid] = (float)simc;

    // valid = count of demo_nodes[b,0,l] > 0 over full L (r0 row fully staged)
    const int valid = __syncthreads_count(tid < LLEN && s_nodes[tid] > 0);

    // sim-linear + bias (pre-LN h), LN partials
    #pragma unroll
    for (int it = 0; it < 2; it++) {
        int i = tid + it * 256;
        if (i < nitems) {
            int lr = i >> 3, q = i & 7;
            float sim = s_sim[lr];
            float4 wv = *(const float4*)&s_ws[q * 4];
            float4 bv = *(const float4*)&s_bs[q * 4];
            float4 h = hreg[it];
            h.x = fmaf(sim, wv.x, h.x) * (1.f / RNUM) + bv.x;
            h.y = fmaf(sim, wv.y, h.y) * (1.f / RNUM) + bv.y;
            h.z = fmaf(sim, wv.z, h.z) * (1.f / RNUM) + bv.z;
            h.w = fmaf(sim, wv.w, h.w) * (1.f / RNUM) + bv.w;
            hreg[it] = h;
            s_p1[i] = h.x + h.y + h.z + h.w;
            s_p2[i] = fmaf(h.x, h.x, fmaf(h.y, h.y, fmaf(h.z, h.z, h.w * h.w)));
        }
    }
    __syncthreads();

    // LN stats: one thread per local row
    if (tid < nr) {
        float s = 0.f, ss = 0.f;
        #pragma unroll
        for (int q = 0; q < 8; q++) { s += s_p1[tid * 8 + q]; ss += s_p2[tid * 8 + q]; }
        float mu = s * (1.f / DDIM);
        float var = ss * (1.f / DDIM) - mu * mu;
        s_mu[tid] = mu;
        s_alpha[tid] = rsqrtf(var + 1e-5f);
    }
    __syncthreads();

    // apply LN -> s_hist
    #pragma unroll
    for (int it = 0; it < 2; it++) {
        int i = tid + it * 256;
        if (i < nitems) {
            int lr = i >> 3, q = i & 7;
            float mu = s_mu[lr], al = s_alpha[lr];
            float4 g4 = *(const float4*)&s_lg[q * 4];
            float4 b4 = *(const float4*)&s_lb[q * 4];
            float4 h = hreg[it];
            h.x = (h.x - mu) * al * g4.x + b4.x;
            h.y = (h.y - mu) * al * g4.y + b4.y;
            h.z = (h.z - mu) * al * g4.z + b4.z;
            h.w = (h.w - mu) * al * g4.w + b4.w;
            *(float4*)&s_hist[lr * DDIM + q * 4] = h;
        }
    }
    __syncthreads();

    // xW = hist @ W_gcn (warp per local row, lane = output column)
    {
        float wg[DDIM];
        #pragma unroll
        for (int k = 0; k < DDIM; k++) wg[k] = Wgcn[k * DDIM + lane];
        for (int lr = warp; lr < nr; lr += 8) {
            float acc = 0.f;
            #pragma unroll
            for (int k0 = 0; k0 < DDIM; k0 += 4) {
                float4 hv = *(const float4*)&s_hist[lr * DDIM + k0];
                acc = fmaf(hv.x, wg[k0 + 0], acc);
                acc = fmaf(hv.y, wg[k0 + 1], acc);
                acc = fmaf(hv.z, wg[k0 + 2], acc);
                acc = fmaf(hv.w, wg[k0 + 3], acc);
            }
            s_xW[lr * DDIM + lane] = acc;
        }
    }
    __syncthreads();

    // chain GCN + relu + partial sum over own 50 global rows
    float lsum = 0.f;
    for (int j = warp; j < HALF; j += 8) {
        int l = half * HALF + j;
        int lr = l - l0;
        bool has_in = (l >= 1 && l < valid);
        float o = s_xW[lr * DDIM + lane];
        if (has_in) {
            float degp = (l >= 2 && (l - 1) < valid) ? 2.f : 1.f;
            o = o * 0.5f + s_xW[(lr - 1) * DDIM + lane] * rsqrtf(degp * 2.f);
        }
        lsum += fmaxf(o + s_bg[lane], 0.f);
    }
    s_part[warp][lane] = lsum;
    __syncthreads();

    if (warp == 0) {
        float p = 0.f;
        #pragma unroll
        for (int w = 0; w < 8; w++) p += s_part[w][lane];
        g_pool[(b * 2 + half) * DDIM + lane] = p;
    }
}

// ---------------------------------------------------------------------------
// Kernel 3: one warp per batch element. Combine halves, mean over L, then
// src_emb = pool @ W_out + b_out ; dst_emb = proj[dst] @ W_out + b_out.
// ---------------------------------------------------------------------------
__global__ __launch_bounds__(256) void k_out(const int* __restrict__ dst_ids,
    const float* __restrict__ Wout, const float* __restrict__ bout,
    float* __restrict__ out, int B)
{
    __shared__ __align__(16) float s_Wo[DDIM * DDIM];
    __shared__ float s_bo[DDIM];

    const int tid = threadIdx.x, lane = tid & 31, warp = tid >> 5;
    for (int i = tid; i < DDIM * DDIM; i += 256) s_Wo[i] = Wout[i];
    if (tid < DDIM) s_bo[tid] = bout[tid];
    __syncthreads();

    const int b = blockIdx.x * 8 + warp;
    if (b >= B) return;

    float p = (g_pool[(b * 2 + 0) * DDIM + lane] +
               g_pool[(b * 2 + 1) * DDIM + lane]) * (1.f / LLEN);
    float pd = g_proj[(size_t)dst_ids[b] * DDIM + lane];

    float e  = s_bo[lane];
    float e2 = s_bo[lane];
    #pragma unroll
    for (int k = 0; k < DDIM; k++) {
        float pk  = __shfl_sync(0xffffffffu, p,  k);
        float pdk = __shfl_sync(0xffffffffu, pd, k);
        float w = s_Wo[k * DDIM + lane];
        e  = fmaf(pk,  w, e);
        e2 = fmaf(pdk, w, e2);
    }
    out[b * DDIM + lane] = e;                 // src_emb
    out[B * DDIM + b * DDIM + lane] = e2;     // dst_emb
}

extern "C" void kernel_launch(void* const* d_in, const int* in_sizes, int n_in,
                              void* d_out, int out_size)
{
    const float* feat   = (const float*)d_in[0];   // [N, 128]
    const int*   rnodes = (const int*)  d_in[1];   // [P, 100]
    const int*   ridx   = (const int*)  d_in[2];   // [B, 5]
    const int*   dst    = (const int*)  d_in[4];   // [B]
    const float* Wf = (const float*)d_in[6];
    const float* bf = (const float*)d_in[7];
    const float* ws = (const float*)d_in[8];
    const float* bs = (const float*)d_in[9];
    const float* lg = (const float*)d_in[10];
    const float* lb = (const float*)d_in[11];
    const float* Wg = (const float*)d_in[12];
    const float* bg = (const float*)d_in[13];
    const float* Wo = (const float*)d_in[14];
    const float* bo = (const float*)d_in[15];
    float* out = (float*)d_out;

    int N = in_sizes[0] / FDIM;
    int B = in_sizes[4];
    if (N > NMAX) N = NMAX;
    if (B > BMAX) B = BMAX;

    int nblk = (N + 127) / 128;
    k_proj<<<nblk, 256>>>(feat, Wf, bf, N);
    dim3 gridA(B, 2);
    k_mainA<<<gridA, 256>>>(rnodes, ridx, dst, ws, bs, lg, lb, Wg, bg);
    k_out<<<(B + 7) / 8, 256>>>(dst, Wo, bo, out, B);
}